// round 14
// baseline (speedup 1.0000x reference)
#include <cuda_runtime.h>
#include <cstdint>

#define DD 256
#define WR 129
#define NB 64
#define PI_F 3.14159265358979323846f
#define RUN 8
#define NCH 17                    // ceil(129/8)
#define ZBLK 2048                 // zero-role blocks in the fused row launch
#define FFTBLK (NB * 64)          // 4096 row-FFT blocks (4 real rows each)
#define TOTBLK (ZBLK + FFTBLK)    // 6144; every 3rd block is a zero block

// Scratch: row/col-FFT intermediate [B, D, WR] complex; interleaved
// accumulation volume [D, D, WR] of float4 (re, im, w, ctf^2).
__device__ float2 g_f[(size_t)NB * DD * WR];
__device__ float4 g_vol[(size_t)DD * DD * WR];

__device__ __forceinline__ float2 cadd(float2 a, float2 b) { return make_float2(a.x + b.x, a.y + b.y); }
__device__ __forceinline__ float2 csub(float2 a, float2 b) { return make_float2(a.x - b.x, a.y - b.y); }
__device__ __forceinline__ float2 cmul(float2 a, float2 b) {
    return make_float2(a.x * b.x - a.y * b.y, a.x * b.y + a.y * b.x);
}

__device__ __forceinline__ void red_add_v4(float4* addr, float4 v) {
    asm volatile("red.global.add.v4.f32 [%0], {%1, %2, %3, %4};"
                 :: "l"(addr), "f"(v.x), "f"(v.y), "f"(v.z), "f"(v.w) : "memory");
}

__device__ __forceinline__ void flush_corner(int z, int y, int x, float4 v) {
    if ((unsigned)z < DD && (unsigned)y < DD && (unsigned)x < WR && v.z != 0.0f)
        red_add_v4(&g_vol[((size_t)z * DD + y) * WR + x], v);
}

// tw[j] = exp(-2*pi*i*j/256), j < 128.
__device__ __forceinline__ void init_twiddles(float2* tw, int t) {
    float ang = (2.0f * PI_F / 256.0f) * (float)t;
    float s, c;
    sincosf(ang, &s, &c);
    tw[t] = make_float2(c, -s);
}

// Fused kernel: every 3rd block zeroes a stripe of g_vol (interleaved with the
// FFT blocks so every wave mixes DRAM-bound and smem-bound roles). FFT blocks:
// 128 threads = two 256-pt complex FFTs (threads 0-63 / 64-127), each packing
// two real rows (A + iB). Radix-2 stage PAIRS fused in registers: 4 shared
// passes + 4 barriers (DIT, bit-reversed input).
__global__ void row_fft_zero_kernel(const float* __restrict__ imgs) {
    if (blockIdx.x % 3 == 2) {
        int zidx = blockIdx.x / 3;               // 0 .. ZBLK-1
        const size_t P = (size_t)DD * DD * WR;
        size_t stride = (size_t)ZBLK * blockDim.x;
        const float4 Z4 = make_float4(0.0f, 0.0f, 0.0f, 0.0f);
        for (size_t i = (size_t)zidx * blockDim.x + threadIdx.x; i < P; i += stride)
            g_vol[i] = Z4;
        return;
    }
    __shared__ float2 sh[2][256];
    __shared__ float2 tw[128];
    int t = threadIdx.x;                         // 128 threads
    init_twiddles(tw, t);
    int fidx = (blockIdx.x / 3) * 2 + (blockIdx.x % 3);   // 0 .. FFTBLK-1
    int b = fidx >> 6;
    int r = fidx & 63;
    int f = t >> 6;                              // which FFT in this block
    int u = t & 63;                              // lane within the FFT
    const float* A  = imgs + ((size_t)b * DD + 4 * r + 2 * f) * DD;
    const float* Bv = A + DD;
    float2* s = sh[f];
#pragma unroll
    for (int m = 0; m < 4; m++) {
        int k = u + 64 * m;
        int kr = __brev(k) >> 24;
        s[k] = make_float2(A[kr], Bv[kr]);
    }
    __syncthreads();
#pragma unroll
    for (int hh = 0; hh < 4; hh++) {             // fused DIT pairs: h = 1,4,16,64
        int h = 1 << (2 * hh);
        int j = u & (h - 1);
        int base = (u - j) * 4 + j;              // (u/h)*4h + j
        float2 w1  = tw[j * (128 >> (2 * hh))];
        float2 w2  = tw[j * (64 >> (2 * hh))];
        float2 w2b = tw[j * (64 >> (2 * hh)) + 64];
        float2 u0 = s[base], u1 = s[base + h], u2 = s[base + 2 * h], u3 = s[base + 3 * h];
        float2 v1 = cmul(u1, w1), v3 = cmul(u3, w1);
        float2 t0 = cadd(u0, v1), t1 = csub(u0, v1);
        float2 t2 = cadd(u2, v3), t3 = csub(u2, v3);
        float2 z2 = cmul(t2, w2), z3 = cmul(t3, w2b);
        s[base]         = cadd(t0, z2);
        s[base + 2 * h] = csub(t0, z2);
        s[base + h]     = cadd(t1, z3);
        s[base + 3 * h] = csub(t1, z3);
        __syncthreads();
    }
    float2* dstA = g_f + ((size_t)b * DD + 4 * r + 2 * f) * WR;
    float2* dstB = dstA + WR;
#pragma unroll
    for (int m = 0; m < 2; m++) {
        int k = u + 64 * m;
        float2 Zk = s[k];
        float2 Zn = s[(256 - k) & 255];
        dstA[k] = make_float2(0.5f * (Zk.x + Zn.x), 0.5f * (Zk.y - Zn.y));
        dstB[k] = make_float2(0.5f * (Zk.y + Zn.y), -0.5f * (Zk.x - Zn.x));
    }
    if (u == 0) {
        float2 Zk = s[128];
        dstA[128] = make_float2(Zk.x, 0.0f);
        dstB[128] = make_float2(Zk.y, 0.0f);
    }
}

// Column FFT along y for 16 columns per block, radix-4 (fused radix-2 pair)
// DIF: 4 shared passes. Shared row i holds frequency brev8(i) afterwards;
// write index brev8(i)^128 folds bit-reversal + fftshift. Coalesced I/O.
__global__ void col_fft_kernel() {
    __shared__ float2 sh[256][17];
    __shared__ float2 tw[128];
    int t = threadIdx.x;                 // 256 threads
    if (t < 128) init_twiddles(tw, t);
    int b = blockIdx.x / 9;
    int tile = blockIdx.x - b * 9;
    int x0 = tile * 16;
    int c = t & 15;
    int g = t >> 4;
    int x = x0 + c;
    bool act = x < WR;
    float2* base = g_f + (size_t)b * DD * WR;
#pragma unroll
    for (int i = 0; i < 16; i++) {
        int row = i * 16 + g;
        sh[row][c] = act ? base[(size_t)row * WR + x] : make_float2(0.0f, 0.0f);
    }
    __syncthreads();
#pragma unroll
    for (int ss = 0; ss < 4; ss++) {
        int s = 2 * ss;
        int Hh = 64 >> s;                    // 64,16,4,1
#pragma unroll
        for (int k = 0; k < 4; k++) {
            int q = g * 4 + k;               // 0..63
            int j = q & (Hh - 1);
            int i = (q - j) * 4 + j;
            float2 wA = tw[j << s];
            float2 wB = tw[(j + Hh) << s];
            float2 wC = tw[j << (s + 1)];
            float2 u0 = sh[i][c];
            float2 u1 = sh[i + Hh][c];
            float2 u2 = sh[i + 2 * Hh][c];
            float2 u3 = sh[i + 3 * Hh][c];
            float2 a0 = cadd(u0, u2);
            float2 a2 = cmul(csub(u0, u2), wA);
            float2 a1 = cadd(u1, u3);
            float2 a3 = cmul(csub(u1, u3), wB);
            sh[i][c]          = cadd(a0, a1);
            sh[i + Hh][c]     = cmul(csub(a0, a1), wC);
            sh[i + 2 * Hh][c] = cadd(a2, a3);
            sh[i + 3 * Hh][c] = cmul(csub(a2, a3), wC);
        }
        __syncthreads();
    }
    if (act) {
#pragma unroll
        for (int i = 0; i < 16; i++) {
            int row = i * 16 + g;
            int yd = (__brev(row) >> 24) ^ 128;
            base[(size_t)yd * WR + x] = sh[row][c];
        }
    }
}

// Scatter with PARITY-INDEXED run-merging: the 8 corner accumulators are
// indexed by absolute coordinate parity (Z&1, Y&1, X&1), which is invariant
// as the trilinear cube slides. Surviving corners never move between
// registers; a slot is flushed+zeroed exactly when its absolute coordinate
// (from the old base) exits the new cube — one uniform 8-site predicate that
// also covers far jumps / Hermitian-fold crossings with no separate path.
__global__ void __launch_bounds__(128, 5)
scatter_kernel(const float* __restrict__ ctf,
               const float* __restrict__ rotm,
               const float* __restrict__ hw) {
    int tid = blockIdx.x * blockDim.x + threadIdx.x;
    const int TT = NB * DD * NCH;
    if (tid >= TT) return;
    int ch = tid % NCH;
    int t2 = tid / NCH;
    int y = t2 & 255;
    int b = t2 >> 8;
    int xs = ch * RUN;
    int n = min(RUN, WR - xs);

    size_t rowoff = ((size_t)b * DD + y) * WR + xs;

    float2 fv8[RUN];
    float cv8[RUN];
#pragma unroll
    for (int i = 0; i < RUN; i++)
        if (i < n) fv8[i] = __ldg(&g_f[rowoff + i]);
#pragma unroll
    for (int i = 0; i < RUN; i++)
        if (i < n) cv8[i] = __ldg(&ctf[rowoff + i]);

    float ky = (float)(y - 128);
    float sy = hw[2 * b + 0];
    float sx = hw[2 * b + 1];
    const float* M = rotm + b * 9;
    float m2 = M[2], m5 = M[5], m8 = M[8];
    float p0 = M[1] * ky, p1 = M[4] * ky, p2 = M[7] * ky;

    const float C = -2.0f * PI_F / 256.0f;
    float cs, sn, cd, sd;
    sincosf(C * (ky * sy + (float)xs * sx), &sn, &cs);
    sincosf(C * sx, &sd, &cd);

    // parity-indexed accumulators: slot bits (pz<<2)|(py<<1)|px
    float4 a0, a1, a2, a3, a4, a5, a6, a7;
    const float4 Z4 = make_float4(0.0f, 0.0f, 0.0f, 0.0f);
    a0 = a1 = a2 = a3 = a4 = a5 = a6 = a7 = Z4;
    int bz = 0, by_ = 0, bx = 0;
    bool have = false;

#pragma unroll
    for (int i = 0; i < RUN; i++) {
        if (i >= n) break;
        float kx = (float)(xs + i);
        float2 f = fv8[i];
        float cv = cv8[i];

        float vr = cv * (f.x * cs - f.y * sn);
        float vi = cv * (f.x * sn + f.y * cs);
        float csq = cv * cv;
        float ncs = cs * cd - sn * sd;
        float nsn = sn * cd + cs * sd;
        cs = ncs; sn = nsn;

        float r0 = p0 + m2 * kx;
        float r1 = p1 + m5 * kx;
        float r2 = p2 + m8 * kx;
        if (r2 < 0.0f) { r0 = -r0; r1 = -r1; r2 = -r2; vi = -vi; }

        float zc = r0 + 128.0f, yc = r1 + 128.0f, xc = r2;
        float z0f = floorf(zc), y0f = floorf(yc), x0f = floorf(xc);
        float fz = zc - z0f, fy = yc - y0f, fx = xc - x0f;
        int z0 = (int)z0f, y0 = (int)y0f, x0 = (int)x0f;
        float gz = 1.0f - fz, gy = 1.0f - fy, gx = 1.0f - fx;

        if (have) {
            // old absolute coords per parity slot
            int oz0 = bz  + (bz  & 1), oz1 = bz  + 1 - (bz  & 1);
            int oy0 = by_ + (by_ & 1), oy1 = by_ + 1 - (by_ & 1);
            int ox0 = bx  + (bx  & 1), ox1 = bx  + 1 - (bx  & 1);
            // exit tests: old coord outside the new cube [c0, c0+1]
            bool ez0 = (unsigned)(oz0 - z0) > 1u;
            bool ez1 = (unsigned)(oz1 - z0) > 1u;
            bool ey0 = (unsigned)(oy0 - y0) > 1u;
            bool ey1 = (unsigned)(oy1 - y0) > 1u;
            bool ex0 = (unsigned)(ox0 - x0) > 1u;
            bool ex1 = (unsigned)(ox1 - x0) > 1u;
            if (ez0 | ey0 | ex0) { flush_corner(oz0, oy0, ox0, a0); a0 = Z4; }
            if (ez0 | ey0 | ex1) { flush_corner(oz0, oy0, ox1, a1); a1 = Z4; }
            if (ez0 | ey1 | ex0) { flush_corner(oz0, oy1, ox0, a2); a2 = Z4; }
            if (ez0 | ey1 | ex1) { flush_corner(oz0, oy1, ox1, a3); a3 = Z4; }
            if (ez1 | ey0 | ex0) { flush_corner(oz1, oy0, ox0, a4); a4 = Z4; }
            if (ez1 | ey0 | ex1) { flush_corner(oz1, oy0, ox1, a5); a5 = Z4; }
            if (ez1 | ey1 | ex0) { flush_corner(oz1, oy1, ox0, a6); a6 = Z4; }
            if (ez1 | ey1 | ex1) { flush_corner(oz1, oy1, ox1, a7); a7 = Z4; }
        }
        // route weights to parity slots: slot parity == coord parity -> g (d=0)
        int qz = z0 & 1, qy = y0 & 1, qx = x0 & 1;
        float wzp0 = qz ? fz : gz, wzp1 = qz ? gz : fz;
        float wyp0 = qy ? fy : gy, wyp1 = qy ? gy : fy;
        float wxp0 = qx ? fx : gx, wxp1 = qx ? gx : fx;
        float v00 = wzp0 * wyp0, v01 = wzp0 * wyp1;
        float v10 = wzp1 * wyp0, v11 = wzp1 * wyp1;
        float w0 = v00 * wxp0, w1 = v00 * wxp1;
        float w2 = v01 * wxp0, w3 = v01 * wxp1;
        float w4 = v10 * wxp0, w5 = v10 * wxp1;
        float w6 = v11 * wxp0, w7 = v11 * wxp1;
        a0.x += w0*vr; a0.y += w0*vi; a0.z += w0; a0.w += w0*csq;
        a1.x += w1*vr; a1.y += w1*vi; a1.z += w1; a1.w += w1*csq;
        a2.x += w2*vr; a2.y += w2*vi; a2.z += w2; a2.w += w2*csq;
        a3.x += w3*vr; a3.y += w3*vi; a3.z += w3; a3.w += w3*csq;
        a4.x += w4*vr; a4.y += w4*vi; a4.z += w4; a4.w += w4*csq;
        a5.x += w5*vr; a5.y += w5*vi; a5.z += w5; a5.w += w5*csq;
        a6.x += w6*vr; a6.y += w6*vi; a6.z += w6; a6.w += w6*csq;
        a7.x += w7*vr; a7.y += w7*vi; a7.z += w7; a7.w += w7*csq;
        bz = z0; by_ = y0; bx = x0; have = true;
    }
    if (have) {
        int oz0 = bz  + (bz  & 1), oz1 = bz  + 1 - (bz  & 1);
        int oy0 = by_ + (by_ & 1), oy1 = by_ + 1 - (by_ & 1);
        int ox0 = bx  + (bx  & 1), ox1 = bx  + 1 - (bx  & 1);
        flush_corner(oz0, oy0, ox0, a0);
        flush_corner(oz0, oy0, ox1, a1);
        flush_corner(oz0, oy1, ox0, a2);
        flush_corner(oz0, oy1, ox1, a3);
        flush_corner(oz1, oy0, ox0, a4);
        flush_corner(oz1, oy0, ox1, a5);
        flush_corner(oz1, oy1, ox0, a6);
        flush_corner(oz1, oy1, ox1, a7);
    }
}

// De-interleave: each thread transposes 4 consecutive float4s into one
// 16B store per output plane. Streaming loads (no reuse of g_vol).
__global__ void finalize_kernel(float* __restrict__ out) {
    const size_t P = (size_t)DD * DD * WR;      // divisible by 4
    const size_t Q = P / 4;
    size_t stride = (size_t)gridDim.x * blockDim.x;
    float4* o0 = (float4*)out;
    float4* o1 = (float4*)(out + P);
    float4* o2 = (float4*)(out + 2 * P);
    float4* o3 = (float4*)(out + 3 * P);
    for (size_t q = (size_t)blockIdx.x * blockDim.x + threadIdx.x; q < Q; q += stride) {
        float4 v0 = __ldcs(&g_vol[4 * q + 0]);
        float4 v1 = __ldcs(&g_vol[4 * q + 1]);
        float4 v2 = __ldcs(&g_vol[4 * q + 2]);
        float4 v3 = __ldcs(&g_vol[4 * q + 3]);
        o0[q] = make_float4(v0.x, v1.x, v2.x, v3.x);
        o1[q] = make_float4(v0.y, v1.y, v2.y, v3.y);
        o2[q] = make_float4(v0.z, v1.z, v2.z, v3.z);
        o3[q] = make_float4(v0.w, v1.w, v2.w, v3.w);
    }
}

extern "C" void kernel_launch(void* const* d_in, const int* in_sizes, int n_in,
                              void* d_out, int out_size) {
    const float* imgs = (const float*)d_in[0];
    const float* ctf  = (const float*)d_in[1];
    const float* rotm = (const float*)d_in[2];
    const float* hw   = (const float*)d_in[3];
    float* out = (float*)d_out;

    row_fft_zero_kernel<<<TOTBLK, 128>>>(imgs);
    col_fft_kernel<<<NB * 9, 256>>>();
    const int TT = NB * DD * NCH;
    scatter_kernel<<<(TT + 127) / 128, 128>>>(ctf, rotm, hw);
    finalize_kernel<<<4096, 256>>>(out);
}

// round 15
// speedup vs baseline: 1.3276x; 1.3276x over previous
#include <cuda_runtime.h>
#include <cstdint>

#define DD 256
#define WR 129
#define NB 64
#define PI_F 3.14159265358979323846f
#define RUN 8
#define NCH 17                    // ceil(129/8)
#define ZBLK 2048                 // zero-role blocks in the fused row launch
#define FFTBLK (NB * 64)          // 4096 row-FFT blocks (4 real rows each)
#define TOTBLK (ZBLK + FFTBLK)    // 6144; every 3rd block is a zero block

// Scratch: row/col-FFT intermediate [B, D, WR] complex; interleaved
// accumulation volume [D, D, WR] of float4 (re, im, w, ctf^2).
__device__ float2 g_f[(size_t)NB * DD * WR];
__device__ float4 g_vol[(size_t)DD * DD * WR];

__device__ __forceinline__ float2 cadd(float2 a, float2 b) { return make_float2(a.x + b.x, a.y + b.y); }
__device__ __forceinline__ float2 csub(float2 a, float2 b) { return make_float2(a.x - b.x, a.y - b.y); }
__device__ __forceinline__ float2 cmul(float2 a, float2 b) {
    return make_float2(a.x * b.x - a.y * b.y, a.x * b.y + a.y * b.x);
}

__device__ __forceinline__ void red_add_v4(float4* addr, float4 v) {
    asm volatile("red.global.add.v4.f32 [%0], {%1, %2, %3, %4};"
                 :: "l"(addr), "f"(v.x), "f"(v.y), "f"(v.z), "f"(v.w) : "memory");
}

__device__ __forceinline__ void flush_corner(int z, int y, int x, float4 v) {
    if ((unsigned)z < DD && (unsigned)y < DD && (unsigned)x < WR && v.z != 0.0f)
        red_add_v4(&g_vol[((size_t)z * DD + y) * WR + x], v);
}

// tw[j] = exp(-2*pi*i*j/256), j < 128.
__device__ __forceinline__ void init_twiddles(float2* tw, int t) {
    float ang = (2.0f * PI_F / 256.0f) * (float)t;
    float s, c;
    sincosf(ang, &s, &c);
    tw[t] = make_float2(c, -s);
}

// Fused kernel: every 3rd block zeroes a stripe of g_vol (interleaved with the
// FFT blocks so every wave mixes DRAM-bound and smem-bound roles). FFT blocks:
// 128 threads = two 256-pt complex FFTs (threads 0-63 / 64-127), each packing
// two real rows (A + iB). Radix-2 stage PAIRS fused in registers: 4 shared
// passes + 4 barriers (DIT, bit-reversed input).
__global__ void row_fft_zero_kernel(const float* __restrict__ imgs) {
    if (blockIdx.x % 3 == 2) {
        int zidx = blockIdx.x / 3;               // 0 .. ZBLK-1
        const size_t P = (size_t)DD * DD * WR;
        size_t stride = (size_t)ZBLK * blockDim.x;
        const float4 Z4 = make_float4(0.0f, 0.0f, 0.0f, 0.0f);
#pragma unroll 4
        for (size_t i = (size_t)zidx * blockDim.x + threadIdx.x; i < P; i += stride)
            g_vol[i] = Z4;
        return;
    }
    __shared__ float2 sh[2][256];
    __shared__ float2 tw[128];
    int t = threadIdx.x;                         // 128 threads
    init_twiddles(tw, t);
    int fidx = (blockIdx.x / 3) * 2 + (blockIdx.x % 3);   // 0 .. FFTBLK-1
    int b = fidx >> 6;
    int r = fidx & 63;
    int f = t >> 6;                              // which FFT in this block
    int u = t & 63;                              // lane within the FFT
    const float* A  = imgs + ((size_t)b * DD + 4 * r + 2 * f) * DD;
    const float* Bv = A + DD;
    float2* s = sh[f];
#pragma unroll
    for (int m = 0; m < 4; m++) {
        int k = u + 64 * m;
        int kr = __brev(k) >> 24;
        s[k] = make_float2(A[kr], Bv[kr]);
    }
    __syncthreads();
#pragma unroll
    for (int hh = 0; hh < 4; hh++) {             // fused DIT pairs: h = 1,4,16,64
        int h = 1 << (2 * hh);
        int j = u & (h - 1);
        int base = (u - j) * 4 + j;              // (u/h)*4h + j
        float2 w1  = tw[j * (128 >> (2 * hh))];
        float2 w2  = tw[j * (64 >> (2 * hh))];
        float2 w2b = tw[j * (64 >> (2 * hh)) + 64];
        float2 u0 = s[base], u1 = s[base + h], u2 = s[base + 2 * h], u3 = s[base + 3 * h];
        float2 v1 = cmul(u1, w1), v3 = cmul(u3, w1);
        float2 t0 = cadd(u0, v1), t1 = csub(u0, v1);
        float2 t2 = cadd(u2, v3), t3 = csub(u2, v3);
        float2 z2 = cmul(t2, w2), z3 = cmul(t3, w2b);
        s[base]         = cadd(t0, z2);
        s[base + 2 * h] = csub(t0, z2);
        s[base + h]     = cadd(t1, z3);
        s[base + 3 * h] = csub(t1, z3);
        __syncthreads();
    }
    float2* dstA = g_f + ((size_t)b * DD + 4 * r + 2 * f) * WR;
    float2* dstB = dstA + WR;
#pragma unroll
    for (int m = 0; m < 2; m++) {
        int k = u + 64 * m;
        float2 Zk = s[k];
        float2 Zn = s[(256 - k) & 255];
        dstA[k] = make_float2(0.5f * (Zk.x + Zn.x), 0.5f * (Zk.y - Zn.y));
        dstB[k] = make_float2(0.5f * (Zk.y + Zn.y), -0.5f * (Zk.x - Zn.x));
    }
    if (u == 0) {
        float2 Zk = s[128];
        dstA[128] = make_float2(Zk.x, 0.0f);
        dstB[128] = make_float2(Zk.y, 0.0f);
    }
}

// Column FFT along y for 16 columns per block, radix-4 (fused radix-2 pair)
// DIF: 4 shared passes. Shared row i holds frequency brev8(i) afterwards;
// write index brev8(i)^128 folds bit-reversal + fftshift. Coalesced I/O.
__global__ void col_fft_kernel() {
    __shared__ float2 sh[256][17];
    __shared__ float2 tw[128];
    int t = threadIdx.x;                 // 256 threads
    if (t < 128) init_twiddles(tw, t);
    int b = blockIdx.x / 9;
    int tile = blockIdx.x - b * 9;
    int x0 = tile * 16;
    int c = t & 15;
    int g = t >> 4;
    int x = x0 + c;
    bool act = x < WR;
    float2* base = g_f + (size_t)b * DD * WR;
#pragma unroll
    for (int i = 0; i < 16; i++) {
        int row = i * 16 + g;
        sh[row][c] = act ? base[(size_t)row * WR + x] : make_float2(0.0f, 0.0f);
    }
    __syncthreads();
#pragma unroll
    for (int ss = 0; ss < 4; ss++) {
        int s = 2 * ss;
        int Hh = 64 >> s;                    // 64,16,4,1
#pragma unroll
        for (int k = 0; k < 4; k++) {
            int q = g * 4 + k;               // 0..63
            int j = q & (Hh - 1);
            int i = (q - j) * 4 + j;
            float2 wA = tw[j << s];
            float2 wB = tw[(j + Hh) << s];
            float2 wC = tw[j << (s + 1)];
            float2 u0 = sh[i][c];
            float2 u1 = sh[i + Hh][c];
            float2 u2 = sh[i + 2 * Hh][c];
            float2 u3 = sh[i + 3 * Hh][c];
            float2 a0 = cadd(u0, u2);
            float2 a2 = cmul(csub(u0, u2), wA);
            float2 a1 = cadd(u1, u3);
            float2 a3 = cmul(csub(u1, u3), wB);
            sh[i][c]          = cadd(a0, a1);
            sh[i + Hh][c]     = cmul(csub(a0, a1), wC);
            sh[i + 2 * Hh][c] = cadd(a2, a3);
            sh[i + 3 * Hh][c] = cmul(csub(a2, a3), wC);
        }
        __syncthreads();
    }
    if (act) {
#pragma unroll
        for (int i = 0; i < 16; i++) {
            int row = i * 16 + g;
            int yd = (__brev(row) >> 24) ^ 128;
            base[(size_t)yd * WR + x] = sh[row][c];
        }
    }
}

// Scatter with run-merging over RUN=8 samples (R9/R13-proven walk) at
// 128-thread blocks, 5 blocks/SM.
__global__ void __launch_bounds__(128, 5)
scatter_kernel(const float* __restrict__ ctf,
               const float* __restrict__ rotm,
               const float* __restrict__ hw) {
    int tid = blockIdx.x * blockDim.x + threadIdx.x;
    const int TT = NB * DD * NCH;
    if (tid >= TT) return;
    int ch = tid % NCH;
    int t2 = tid / NCH;
    int y = t2 & 255;
    int b = t2 >> 8;
    int xs = ch * RUN;
    int n = min(RUN, WR - xs);

    size_t rowoff = ((size_t)b * DD + y) * WR + xs;

    float2 fv8[RUN];
    float cv8[RUN];
#pragma unroll
    for (int i = 0; i < RUN; i++)
        if (i < n) fv8[i] = __ldg(&g_f[rowoff + i]);
#pragma unroll
    for (int i = 0; i < RUN; i++)
        if (i < n) cv8[i] = __ldg(&ctf[rowoff + i]);

    float ky = (float)(y - 128);
    float sy = hw[2 * b + 0];
    float sx = hw[2 * b + 1];
    const float* M = rotm + b * 9;
    float m2 = M[2], m5 = M[5], m8 = M[8];
    float p0 = M[1] * ky, p1 = M[4] * ky, p2 = M[7] * ky;

    const float C = -2.0f * PI_F / 256.0f;
    float cs, sn, cd, sd;
    sincosf(C * (ky * sy + (float)xs * sx), &sn, &cs);
    sincosf(C * sx, &sd, &cd);

    float4 a0, a1, a2, a3, a4, a5, a6, a7;   // corner bits: (z<<2)|(y<<1)|x
    const float4 Z4 = make_float4(0.0f, 0.0f, 0.0f, 0.0f);
    a0 = a1 = a2 = a3 = a4 = a5 = a6 = a7 = Z4;
    int bz = 0, by_ = 0, bx = 0;
    bool have = false;

#pragma unroll
    for (int i = 0; i < RUN; i++) {
        if (i >= n) break;
        int x = xs + i;
        float kx = (float)x;
        float2 f = fv8[i];
        float cv = cv8[i];

        float vr = cv * (f.x * cs - f.y * sn);
        float vi = cv * (f.x * sn + f.y * cs);
        float csq = cv * cv;
        float ncs = cs * cd - sn * sd;
        float nsn = sn * cd + cs * sd;
        cs = ncs; sn = nsn;

        float r0 = p0 + m2 * kx;
        float r1 = p1 + m5 * kx;
        float r2 = p2 + m8 * kx;
        if (r2 < 0.0f) { r0 = -r0; r1 = -r1; r2 = -r2; vi = -vi; }

        float zc = r0 + 128.0f, yc = r1 + 128.0f, xc = r2;
        float z0f = floorf(zc), y0f = floorf(yc), x0f = floorf(xc);
        float fz = zc - z0f, fy = yc - y0f, fx = xc - x0f;
        int z0 = (int)z0f, y0 = (int)y0f, x0 = (int)x0f;
        float gz = 1.0f - fz, gy = 1.0f - fy, gx = 1.0f - fx;
        float w0 = gz * gy * gx, w1 = gz * gy * fx;
        float w2 = gz * fy * gx, w3 = gz * fy * fx;
        float w4 = fz * gy * gx, w5 = fz * gy * fx;
        float w6 = fz * fy * gx, w7 = fz * fy * fx;

        bool reinit = !have;
        if (have) {
            int dz = z0 - bz, dy = y0 - by_, dx = x0 - bx;
            if ((unsigned)(dz + 1) > 2u || (unsigned)(dy + 1) > 2u ||
                (unsigned)(dx + 1) > 2u) {
                flush_corner(bz,     by_,     bx,     a0);
                flush_corner(bz,     by_,     bx + 1, a1);
                flush_corner(bz,     by_ + 1, bx,     a2);
                flush_corner(bz,     by_ + 1, bx + 1, a3);
                flush_corner(bz + 1, by_,     bx,     a4);
                flush_corner(bz + 1, by_,     bx + 1, a5);
                flush_corner(bz + 1, by_ + 1, bx,     a6);
                flush_corner(bz + 1, by_ + 1, bx + 1, a7);
                reinit = true;
            } else {
#define SURV(oz, oy, ox) (((unsigned)((oz) - dz) <= 1u) && \
                          ((unsigned)((oy) - dy) <= 1u) && \
                          ((unsigned)((ox) - dx) <= 1u))
                if (!SURV(0,0,0)) flush_corner(bz,     by_,     bx,     a0);
                if (!SURV(0,0,1)) flush_corner(bz,     by_,     bx + 1, a1);
                if (!SURV(0,1,0)) flush_corner(bz,     by_ + 1, bx,     a2);
                if (!SURV(0,1,1)) flush_corner(bz,     by_ + 1, bx + 1, a3);
                if (!SURV(1,0,0)) flush_corner(bz + 1, by_,     bx,     a4);
                if (!SURV(1,0,1)) flush_corner(bz + 1, by_,     bx + 1, a5);
                if (!SURV(1,1,0)) flush_corner(bz + 1, by_ + 1, bx,     a6);
                if (!SURV(1,1,1)) flush_corner(bz + 1, by_ + 1, bx + 1, a7);
#undef SURV
                if (dz == 1)       { a0=a4; a1=a5; a2=a6; a3=a7; a4=Z4; a5=Z4; a6=Z4; a7=Z4; }
                else if (dz == -1) { a4=a0; a5=a1; a6=a2; a7=a3; a0=Z4; a1=Z4; a2=Z4; a3=Z4; }
                if (dy == 1)       { a0=a2; a1=a3; a4=a6; a5=a7; a2=Z4; a3=Z4; a6=Z4; a7=Z4; }
                else if (dy == -1) { a2=a0; a3=a1; a6=a4; a7=a5; a0=Z4; a1=Z4; a4=Z4; a5=Z4; }
                if (dx == 1)       { a0=a1; a2=a3; a4=a5; a6=a7; a1=Z4; a3=Z4; a5=Z4; a7=Z4; }
                else if (dx == -1) { a1=a0; a3=a2; a5=a4; a7=a6; a0=Z4; a2=Z4; a4=Z4; a6=Z4; }
                bz = z0; by_ = y0; bx = x0;
                a0.x += w0*vr; a0.y += w0*vi; a0.z += w0; a0.w += w0*csq;
                a1.x += w1*vr; a1.y += w1*vi; a1.z += w1; a1.w += w1*csq;
                a2.x += w2*vr; a2.y += w2*vi; a2.z += w2; a2.w += w2*csq;
                a3.x += w3*vr; a3.y += w3*vi; a3.z += w3; a3.w += w3*csq;
                a4.x += w4*vr; a4.y += w4*vi; a4.z += w4; a4.w += w4*csq;
                a5.x += w5*vr; a5.y += w5*vi; a5.z += w5; a5.w += w5*csq;
                a6.x += w6*vr; a6.y += w6*vi; a6.z += w6; a6.w += w6*csq;
                a7.x += w7*vr; a7.y += w7*vi; a7.z += w7; a7.w += w7*csq;
            }
        }
        if (reinit) {
            bz = z0; by_ = y0; bx = x0; have = true;
            a0 = make_float4(w0*vr, w0*vi, w0, w0*csq);
            a1 = make_float4(w1*vr, w1*vi, w1, w1*csq);
            a2 = make_float4(w2*vr, w2*vi, w2, w2*csq);
            a3 = make_float4(w3*vr, w3*vi, w3, w3*csq);
            a4 = make_float4(w4*vr, w4*vi, w4, w4*csq);
            a5 = make_float4(w5*vr, w5*vi, w5, w5*csq);
            a6 = make_float4(w6*vr, w6*vi, w6, w6*csq);
            a7 = make_float4(w7*vr, w7*vi, w7, w7*csq);
        }
    }
    if (have) {
        flush_corner(bz,     by_,     bx,     a0);
        flush_corner(bz,     by_,     bx + 1, a1);
        flush_corner(bz,     by_ + 1, bx,     a2);
        flush_corner(bz,     by_ + 1, bx + 1, a3);
        flush_corner(bz + 1, by_,     bx,     a4);
        flush_corner(bz + 1, by_,     bx + 1, a5);
        flush_corner(bz + 1, by_ + 1, bx,     a6);
        flush_corner(bz + 1, by_ + 1, bx + 1, a7);
    }
}

// De-interleave: each thread transposes 4 consecutive float4s into one
// 16B store per output plane. Streaming loads AND stores (no reuse either
// side — keep this kernel's working set out of L2).
__global__ void finalize_kernel(float* __restrict__ out) {
    const size_t P = (size_t)DD * DD * WR;      // divisible by 4
    const size_t Q = P / 4;
    size_t stride = (size_t)gridDim.x * blockDim.x;
    float4* o0 = (float4*)out;
    float4* o1 = (float4*)(out + P);
    float4* o2 = (float4*)(out + 2 * P);
    float4* o3 = (float4*)(out + 3 * P);
    for (size_t q = (size_t)blockIdx.x * blockDim.x + threadIdx.x; q < Q; q += stride) {
        float4 v0 = __ldcs(&g_vol[4 * q + 0]);
        float4 v1 = __ldcs(&g_vol[4 * q + 1]);
        float4 v2 = __ldcs(&g_vol[4 * q + 2]);
        float4 v3 = __ldcs(&g_vol[4 * q + 3]);
        __stcs(&o0[q], make_float4(v0.x, v1.x, v2.x, v3.x));
        __stcs(&o1[q], make_float4(v0.y, v1.y, v2.y, v3.y));
        __stcs(&o2[q], make_float4(v0.z, v1.z, v2.z, v3.z));
        __stcs(&o3[q], make_float4(v0.w, v1.w, v2.w, v3.w));
    }
}

extern "C" void kernel_launch(void* const* d_in, const int* in_sizes, int n_in,
                              void* d_out, int out_size) {
    const float* imgs = (const float*)d_in[0];
    const float* ctf  = (const float*)d_in[1];
    const float* rotm = (const float*)d_in[2];
    const float* hw   = (const float*)d_in[3];
    float* out = (float*)d_out;

    row_fft_zero_kernel<<<TOTBLK, 128>>>(imgs);
    col_fft_kernel<<<NB * 9, 256>>>();
    const int TT = NB * DD * NCH;
    scatter_kernel<<<(TT + 127) / 128, 128>>>(ctf, rotm, hw);
    finalize_kernel<<<4096, 256>>>(out);
}